// round 17
// baseline (speedup 1.0000x reference)
#include <cuda_runtime.h>
#include <cuda_fp16.h>
#include <cstdint>

#define Bq 32
#define Sq 48
#define Lq 64
#define Fq 256
#define NTILES (Bq * Sq)
#define GRID 152

// ---------------- staged W1 in mma.sync B-fragment layout (fp16) ----------------
__device__ __align__(16) uint4 g_Wf[16 * 16 * 32];   // 128KB

__device__ __forceinline__ uint32_t pack_h(float lo, float hi) {
    __half2 h = __floats2half2_rn(lo, hi);
    return *reinterpret_cast<uint32_t*>(&h);
}

__global__ void stage_w1_kernel(const float* __restrict__ W1) {
    int idx = blockIdx.x * 256 + threadIdx.x;   // 8192 uint4s
    int lane = idx & 31;
    int nbp  = (idx >> 5) & 15;
    int s    = idx >> 9;
    int g = lane >> 2, q = lane & 3;
    int k0 = s * 16 + q * 2;
    uint4 r;
    uint32_t* rr = reinterpret_cast<uint32_t*>(&r);
    #pragma unroll
    for (int h = 0; h < 2; ++h) {
        int col = (nbp * 2 + h) * 8 + g;
        rr[h * 2 + 0] = pack_h(W1[(k0 + 0) * 256 + col], W1[(k0 + 1) * 256 + col]);
        rr[h * 2 + 1] = pack_h(W1[(k0 + 8) * 256 + col], W1[(k0 + 9) * 256 + col]);
    }
    g_Wf[idx] = r;
}

// ---------------- helpers ----------------
__device__ __forceinline__ uint32_t smem_u32(const void* p) {
    uint32_t a;
    asm("{ .reg .u64 t; cvta.to.shared.u64 t, %1; cvt.u32.u64 %0, t; }" : "=r"(a) : "l"(p));
    return a;
}
__device__ __forceinline__ void cp16(uint32_t dst, const void* src) {
    asm volatile("cp.async.ca.shared.global [%0], [%1], 16;" :: "r"(dst), "l"(src));
}
#define CP_COMMIT()   asm volatile("cp.async.commit_group;" ::: "memory")
#define CP_WAIT_ALL() asm volatile("cp.async.wait_group 0;" ::: "memory")

__device__ __forceinline__ void gbar(int id) {
    asm volatile("bar.sync %0, 256;" :: "r"(id) : "memory");
}

__device__ __forceinline__ void mma16816(float* c, const uint4& a, uint32_t b0, uint32_t b1) {
    asm volatile(
        "mma.sync.aligned.m16n8k16.row.col.f32.f16.f16.f32 "
        "{%0,%1,%2,%3},{%4,%5,%6,%7},{%8,%9},{%0,%1,%2,%3};"
        : "+f"(c[0]), "+f"(c[1]), "+f"(c[2]), "+f"(c[3])
        : "r"(a.x), "r"(a.y), "r"(a.z), "r"(a.w), "r"(b0), "r"(b1));
}

// ---------------- SMEM layout (bytes) ----------------
static constexpr int WF_OFF   = 0;         // resident W1 fragments: 16 x 8KB = 128KB
static constexpr int XF_OFF   = 131072;    // per-group X A-fragments: 2 x 32KB
static constexpr int PRED_OFF = 196608;    // per-group float[256]: 2 x 1KB
static constexpr int P5_OFF   = 198656;    // per-group float4[256]: 2 x 4KB
static constexpr int W2B1_OFF = 206848;    // float2[256] = 2KB (shared)
static constexpr int SC_OFF   = 208896;    // per-group float[64]: 2 x 256B
static constexpr int WGT_OFF  = 209408;    // per-group float[64]: 2 x 256B
static constexpr int SMEM_BYTES = 209920;

// convert one (b,s) tile of X (64x256 f32) into fp16 A-fragment layout (single term)
// layout: [s 16][mtg 4][lane 32] uint4 -> s*2048 + mtg*512 + lane*16 bytes
__device__ __forceinline__ void convert_x(const float4* __restrict__ gx,
                                          char* __restrict__ xf,
                                          int tid, int stride, int iters) {
    #pragma unroll 4
    for (int r = 0; r < iters; ++r) {
        int idx = tid + r * stride;          // float4 index = m*64 + qq
        int m = idx >> 6, qq = idx & 63;
        float4 x = gx[idx];
        int s     = qq >> 2;
        int colk4 = qq & 3;
        int mtg   = m >> 4;
        int half  = (m >> 3) & 1;
        int regIdx = ((colk4 >> 1) << 1) + half;       // 0..3
        int lane0  = (m & 7) * 4 + (colk4 & 1) * 2;
        uint32_t off_h = ((s * 4 + mtg) * 32 + lane0) * 16 + regIdx * 4;
        __half2 h0 = __floats2half2_rn(x.x, x.y);
        __half2 h1 = __floats2half2_rn(x.z, x.w);
        *reinterpret_cast<uint32_t*>(xf + off_h)      = *reinterpret_cast<uint32_t*>(&h0);
        *reinterpret_cast<uint32_t*>(xf + off_h + 16) = *reinterpret_cast<uint32_t*>(&h1);
    }
}

__global__ __launch_bounds__(512, 1)
void ida_pp_kernel(const float* __restrict__ features,
                   const float* __restrict__ src_locs,
                   const float* __restrict__ tar_locs,
                   const float* __restrict__ b1,
                   const float* __restrict__ W2,
                   const float* __restrict__ b2,
                   float* __restrict__ out)
{
    extern __shared__ char smem[];
    const uint32_t sb = smem_u32(smem);
    const int t    = threadIdx.x;
    const int gid  = t >> 8;             // 0 or 1 — independent pipeline
    const int gt   = t & 255;
    const int lane = t & 31;
    const int wid_g = gt >> 5;           // 0..7 within group
    const int warp_m = wid_g & 1;
    const int warp_n = wid_g >> 1;       // 0..3
    const int g = lane >> 2, q = lane & 3;
    const int bid  = blockIdx.x;
    const int T    = (NTILES - 1 - bid) / GRID + 1;   // tiles for this CTA
    const int barid = 1 + gid;

    // per-group scratch
    char* xf_own   = smem + XF_OFF + gid * 32768;
    float* pred    = reinterpret_cast<float*>(smem + PRED_OFF + gid * 1024);
    float4* p54    = reinterpret_cast<float4*>(smem + P5_OFF + gid * 4096);
    float* sc_own  = reinterpret_cast<float*>(smem + SC_OFF + gid * 256);
    float* wg_own  = reinterpret_cast<float*>(smem + WGT_OFF + gid * 256);

    // ---- one-time prologue: resident W1 (128KB) + aux ----
    {
        #pragma unroll
        for (int j = 0; j < 16; ++j) {
            int seg = t + j * 512;               // 8192 uint4s
            cp16(sb + WF_OFF + seg * 16, g_Wf + seg);
        }
        CP_COMMIT();
    }
    if (t < 256) {
        float2* wb = reinterpret_cast<float2*>(smem + W2B1_OFF);
        wb[t] = make_float2(b1[t], W2[t]);
    }
    const float b2v = b2[0];
    CP_WAIT_ALL();
    __syncthreads();

    // ---- independent per-group pipeline: tiles gid, gid+2, gid+4, ... ----
    #pragma unroll 1
    for (int it = gid; it < T; it += 2) {
        const int bs = bid + it * GRID;
        const int b  = bs / Sq;

        // convert own tile (group waits for its own previous phase-5 reads via barriers below)
        convert_x(reinterpret_cast<const float4*>(features + (size_t)bs * (Lq * Fq)),
                  xf_own, gt, 256, 16);
        float invd_reg = 0.f;
        if (gt < Lq) {
            float dx = src_locs[(b * Lq + gt) * 2 + 0] - tar_locs[b * 2 + 0];
            float dy = src_locs[(b * Lq + gt) * 2 + 1] - tar_locs[b * 2 + 1];
            invd_reg = rsqrtf(dx * dx + dy * dy);
        }
        gbar(barid);     // Xf ready for all group warps

        // ---- GEMM: 16 K-steps, pure SMEM, no barriers ----
        float acc[2][8][4];
        #pragma unroll
        for (int mt = 0; mt < 2; ++mt)
            #pragma unroll
            for (int nt = 0; nt < 8; ++nt)
                #pragma unroll
                for (int k = 0; k < 4; ++k) acc[mt][nt][k] = 0.f;

        #pragma unroll 4
        for (int s = 0; s < 16; ++s) {
            const char* wfs = smem + WF_OFF + s * 8192;
            const char* xfs = xf_own + s * 2048;

            uint4 A[2];
            #pragma unroll
            for (int mt = 0; mt < 2; ++mt) {
                int mtg = warp_m * 2 + mt;
                A[mt] = *reinterpret_cast<const uint4*>(xfs + (mtg * 32 + lane) * 16);
            }
            #pragma unroll
            for (int i = 0; i < 4; ++i) {
                uint4 B = *reinterpret_cast<const uint4*>(
                    wfs + ((warp_n * 4 + i) * 32 + lane) * 16);
                mma16816(acc[0][i * 2 + 0], A[0], B.x, B.y);
                mma16816(acc[1][i * 2 + 0], A[1], B.x, B.y);
                mma16816(acc[0][i * 2 + 1], A[0], B.z, B.w);
                mma16816(acc[1][i * 2 + 1], A[1], B.z, B.w);
            }
        }

        // ---- epilogue: p = sum_col relu(D+b1)*W2, quad-reduce ----
        {
            const float2* wb = reinterpret_cast<const float2*>(smem + W2B1_OFF);
            #pragma unroll
            for (int mt = 0; mt < 2; ++mt) {
                float p0 = 0.f, p1 = 0.f;
                #pragma unroll
                for (int nt = 0; nt < 8; ++nt) {
                    int col0 = warp_n * 64 + nt * 8 + q * 2;
                    float2 c0 = wb[col0];
                    float2 c1 = wb[col0 + 1];
                    const float* c = acc[mt][nt];
                    p0 = fmaf(fmaxf(c[0] + c0.x, 0.f), c0.y, p0);
                    p0 = fmaf(fmaxf(c[1] + c1.x, 0.f), c1.y, p0);
                    p1 = fmaf(fmaxf(c[2] + c0.x, 0.f), c0.y, p1);
                    p1 = fmaf(fmaxf(c[3] + c1.x, 0.f), c1.y, p1);
                }
                #pragma unroll
                for (int off = 1; off < 4; off <<= 1) {
                    p0 += __shfl_xor_sync(0xffffffffu, p0, off);
                    p1 += __shfl_xor_sync(0xffffffffu, p1, off);
                }
                if (q == 0) {
                    int row = warp_m * 32 + mt * 16 + g;
                    pred[warp_n * 64 + row]     = p0;
                    pred[warp_n * 64 + row + 8] = p1;
                }
            }
        }
        gbar(barid);
        if (gt < 64) {
            float ptot = pred[gt] + pred[gt + 64] + pred[gt + 128] + pred[gt + 192];
            sc_own[gt] = fmaxf(ptot + b2v, 0.f) * invd_reg;
        }
        gbar(barid);

        // ---- softmax over L=64 (first warp of group) ----
        if (wid_g == 0) {
            float s0 = sc_own[lane], s1 = sc_own[lane + 32];
            float m = fmaxf(s0, s1);
            #pragma unroll
            for (int off = 16; off > 0; off >>= 1)
                m = fmaxf(m, __shfl_xor_sync(0xffffffffu, m, off));
            float e0 = expf(s0 - m), e1 = expf(s1 - m);
            float ssum = e0 + e1;
            #pragma unroll
            for (int off = 16; off > 0; off >>= 1)
                ssum += __shfl_xor_sync(0xffffffffu, ssum, off);
            float inv = 1.f / ssum;
            wg_own[lane] = e0 * inv;
            wg_own[lane + 32] = e1 * inv;
        }
        gbar(barid);

        // ---- phase 5: out[bs,:] = sum_l wgt[l] * features[bs,l,:] (fp32-exact) ----
        {
            const float4* fx = reinterpret_cast<const float4*>(features + (size_t)bs * (Lq * Fq));
            const int fb  = gt & 63;
            const int sub = gt >> 6;          // 0..3 -> l in [sub*16, +16)
            float4 o = make_float4(0.f, 0.f, 0.f, 0.f);
            #pragma unroll 4
            for (int i = 0; i < 16; ++i) {
                int l = sub * 16 + i;
                float w = wg_own[l];
                float4 x = fx[l * 64 + fb];
                o.x = fmaf(w, x.x, o.x);
                o.y = fmaf(w, x.y, o.y);
                o.z = fmaf(w, x.z, o.z);
                o.w = fmaf(w, x.w, o.w);
            }
            p54[gt] = o;
        }
        gbar(barid);
        if (gt < 64) {
            float4 a0 = p54[gt], a1 = p54[gt + 64], a2 = p54[gt + 128], a3 = p54[gt + 192];
            float4 o2;
            o2.x = a0.x + a1.x + a2.x + a3.x;
            o2.y = a0.y + a1.y + a2.y + a3.y;
            o2.z = a0.z + a1.z + a2.z + a3.z;
            o2.w = a0.w + a1.w + a2.w + a3.w;
            reinterpret_cast<float4*>(out + (size_t)bs * Fq)[gt] = o2;
        }
        gbar(barid);   // phase-5 reads done before next convert overwrites Xf scratch
    }
}

extern "C" void kernel_launch(void* const* d_in, const int* in_sizes, int n_in,
                              void* d_out, int out_size)
{
    const float* features = (const float*)d_in[0];
    const float* src_locs = (const float*)d_in[1];
    const float* tar_locs = (const float*)d_in[2];
    const float* W1       = (const float*)d_in[3];
    const float* b1       = (const float*)d_in[4];
    const float* W2       = (const float*)d_in[5];
    const float* b2       = (const float*)d_in[6];
    float* out            = (float*)d_out;

    stage_w1_kernel<<<32, 256>>>(W1);

    cudaFuncSetAttribute(ida_pp_kernel,
                         cudaFuncAttributeMaxDynamicSharedMemorySize, SMEM_BYTES);
    ida_pp_kernel<<<GRID, 512, SMEM_BYTES>>>(
        features, src_locs, tar_locs, b1, W2, b2, out);
}